// round 11
// baseline (speedup 1.0000x reference)
#include <cuda_runtime.h>
#include <cuda_bf16.h>
#include <cstdint>
#include <math.h>

#define BSZ 8
#define HN  512
#define LN  2048
#define D2N 32
#define CN  64          // chunk length
#define NC  (LN/CN)     // 32 chunks

// ---------------- scratch (device globals; no allocation allowed) ----------------
__device__ __align__(16) float  g_f [HN*LN];
__device__ __align__(16) float  g_k0[HN*LN];
__device__ float2               g_V [HN*CN*D2N];      // [h][m][d] = w^{C-1-m}
__device__ __align__(16) float  g_P [HN*2*D2N*CN];    // [h][dd][j]
__device__ float2               g_WC[HN*D2N];         // w^C
__device__ __align__(16) float  g_S [BSZ*HN*NC*2*D2N];
__device__ __align__(16) __nv_bfloat16 g_Wh[HN*HN], g_Wl[HN*HN];
__device__ __align__(16) __nv_bfloat16 g_gh[BSZ*HN*LN], g_gl[BSZ*HN*LN];

// ---------------- shared mma/ldsm helpers ----------------
__device__ __forceinline__ void ldsm_x4(uint32_t &r0, uint32_t &r1, uint32_t &r2, uint32_t &r3,
                                        uint32_t addr) {
    asm volatile("ldmatrix.sync.aligned.m8n8.x4.shared.b16 {%0,%1,%2,%3}, [%4];"
                 : "=r"(r0), "=r"(r1), "=r"(r2), "=r"(r3) : "r"(addr));
}
__device__ __forceinline__ void ldsm_x2t(uint32_t &r0, uint32_t &r1, uint32_t addr) {
    asm volatile("ldmatrix.sync.aligned.m8n8.x2.trans.shared.b16 {%0,%1}, [%2];"
                 : "=r"(r0), "=r"(r1) : "r"(addr));
}
__device__ __forceinline__ void mma_bf16(float* c, const uint32_t* a, const uint32_t* b) {
    asm volatile("mma.sync.aligned.m16n8k16.row.col.f32.bf16.bf16.f32 "
                 "{%0,%1,%2,%3},{%4,%5,%6,%7},{%8,%9},{%0,%1,%2,%3};"
                 : "+f"(c[0]), "+f"(c[1]), "+f"(c[2]), "+f"(c[3])
                 : "r"(a[0]), "r"(a[1]), "r"(a[2]), "r"(a[3]), "r"(b[0]), "r"(b[1]));
}

// ---------------- K1: f/k0 grid via phasor rotation ----------------
__global__ void __launch_bounds__(128) k_tables(const float* __restrict__ a,
                                                const float* __restrict__ th,
                                                const float* __restrict__ bb,
                                                const float* __restrict__ cc,
                                                const float* __restrict__ x0)
{
    int h = blockIdx.x;
    __shared__ float4 tab[D2N];
    __shared__ float s_aa[D2N], s_th[D2N];
    int tid = threadIdx.x;
    const float T = 1.0f / (float)(LN - 1);
    if (tid < D2N) {
        float aa = -fabsf(a[h*D2N + tid]);
        float t0 = th[h*D2N + tid];
        float q  = bb[h*D2N + tid] * cc[h*D2N + tid];
        float cx = cc[h*D2N + tid] * x0[h*D2N + tid];
        s_aa[tid] = aa; s_th[tid] = t0;
        float zs = 128.0f * T;
        float e = __expf(aa*zs);
        float si, co; __sincosf(t0*zs, &si, &co);
        tab[tid] = make_float4(e*co, e*si, q, cx);
    }
    __syncthreads();

    float z = T * (float)tid;
    float vr[D2N], vi[D2N];
    #pragma unroll
    for (int d = 0; d < D2N; d++) {
        float e = __expf(s_aa[d]*z);
        float si, co; __sincosf(s_th[d]*z, &si, &co);
        vr[d] = e*co; vi[d] = e*si;
    }
    for (int s = 0; s < 16; s++) {
        float fa = 0.f, ka = 0.f;
        #pragma unroll
        for (int d = 0; d < D2N; d++) {
            float4 t = tab[d];
            fa += t.z * vr[d];
            ka += t.w * vr[d];
            float nr = vr[d]*t.x - vi[d]*t.y;
            vi[d]    = vr[d]*t.y + vi[d]*t.x;
            vr[d] = nr;
        }
        g_f [h*LN + tid + 128*s] = 2.0f*T*fa;
        g_k0[h*LN + tid + 128*s] = 2.0f*ka;
    }
}

// ---------------- K1b: V/P/WC tables + W bf16 split, merged ----------------
__global__ void k_tables2(const float* __restrict__ a, const float* __restrict__ th,
                          const float* __restrict__ bb, const float* __restrict__ cc,
                          const float* __restrict__ W)
{
    int bid = blockIdx.x;
    if (bid >= 8192) {
        int i = (bid - 8192)*256 + threadIdx.x;
        float w = W[i];
        __nv_bfloat16 hi = __float2bfloat16(w);
        g_Wh[i] = hi;
        g_Wl[i] = __float2bfloat16(w - __bfloat162float(hi));
        return;
    }
    int t = bid*256 + threadIdx.x;
    int which = t >> 20;
    int r = t & 0xFFFFF;
    const float T = 1.0f / (float)(LN - 1);
    if (which == 0) {
        int d = r & 31, m = (r >> 5) & 63, h = r >> 11;
        float aa = -fabsf(a[h*D2N + d]);
        float t0 = th[h*D2N + d];
        float k = (float)(CN - 1 - m);
        float e = __expf(aa*T*k);
        float si, co; __sincosf(t0*T*k, &si, &co);
        g_V[(h*CN + m)*D2N + d] = make_float2(e*co, e*si);
        if (m == 0) {
            float kc = (float)CN;
            float ec = __expf(aa*T*kc);
            float s2, c2; __sincosf(t0*T*kc, &s2, &c2);
            g_WC[h*D2N + d] = make_float2(ec*c2, ec*s2);
        }
    } else {
        int j = r & 63, d = (r >> 6) & 31, h = r >> 11;
        float aa = -fabsf(a[h*D2N + d]);
        float t0 = th[h*D2N + d];
        float q  = bb[h*D2N + d] * cc[h*D2N + d];
        float k = (float)(j + 1);
        float e = __expf(aa*T*k);
        float si, co; __sincosf(t0*T*k, &si, &co);
        g_P[(h*2*D2N + d      )*CN + j] =  2.0f*T*q*e*co;
        g_P[(h*2*D2N + D2N + d)*CN + j] = -2.0f*T*q*e*si;
    }
}

// ---------------- K2: chunk states, register-resident A + 2-level scan ----------------
__global__ void __launch_bounds__(128) k_chunkA(const float* __restrict__ u)
{
    int row = blockIdx.x;
    int h = row & (HN-1);
    __shared__ float  u_s[LN];
    __shared__ float2 V_s[CN*D2N];
    __shared__ float2 Tex[4][D2N];
    __shared__ float2 Off[4][D2N];
    int tid = threadIdx.x;
    for (int i = tid; i < LN/4; i += 128)
        ((float4*)u_s)[i] = ((const float4*)(u + row*LN))[i];
    const float4* Vg4 = (const float4*)(g_V + h*CN*D2N);
    for (int i = tid; i < CN*D2N/2; i += 128)
        ((float4*)V_s)[i] = Vg4[i];
    __syncthreads();

    int d = tid & 31;
    int w = tid >> 5;
    float ar[8] = {}, ai[8] = {};
    #pragma unroll 2
    for (int m4 = 0; m4 < CN; m4 += 4) {
        float4 uv[8];
        #pragma unroll
        for (int c = 0; c < 8; c++)
            uv[c] = *(const float4*)&u_s[(8*w + c)*CN + m4];
        #pragma unroll
        for (int mm = 0; mm < 4; mm++) {
            float2 v = V_s[(m4+mm)*D2N + d];
            #pragma unroll
            for (int c = 0; c < 8; c++) {
                float um = ((const float*)&uv[c])[mm];
                ar[c] += v.x * um;
                ai[c] += v.y * um;
            }
        }
    }

    float2 wc = g_WC[h*D2N + d];
    float Sr[8], Si[8];
    {
        float sr = 0.f, si = 0.f;
        #pragma unroll
        for (int c = 0; c < 8; c++) {
            Sr[c] = sr; Si[c] = si;
            float nsr = wc.x*sr - wc.y*si + ar[c];
            si        = wc.x*si + wc.y*sr + ai[c];
            sr = nsr;
        }
        Tex[w][d] = make_float2(sr, si);
    }
    __syncthreads();

    if (w == 0) {
        float2 w2 = make_float2(wc.x*wc.x - wc.y*wc.y, 2.f*wc.x*wc.y);
        float2 w4 = make_float2(w2.x*w2.x - w2.y*w2.y, 2.f*w2.x*w2.y);
        float2 w8 = make_float2(w4.x*w4.x - w4.y*w4.y, 2.f*w4.x*w4.y);
        float orr = 0.f, oi = 0.f;
        #pragma unroll
        for (int ww = 0; ww < 4; ww++) {
            Off[ww][d] = make_float2(orr, oi);
            float2 t = Tex[ww][d];
            float no = w8.x*orr - w8.y*oi + t.x;
            oi       = w8.x*oi + w8.y*orr + t.y;
            orr = no;
        }
    }
    __syncthreads();

    float2 off = Off[w][d];
    float cr = off.x, ci = off.y;
    #pragma unroll
    for (int c = 0; c < 8; c++) {
        int idx = (row*NC + 8*w + c)*2*D2N;
        g_S[idx + d]       = cr + Sr[c];
        g_S[idx + D2N + d] = ci + Si[c];
        float ncr = wc.x*cr - wc.y*ci;
        ci        = wc.x*ci + wc.y*cr;
        cr = ncr;
    }
}

// ---------------- K4: tensor-core row GEMM  Y = [S|U](32x128) @ [P;F](128x64) ----------------
#define AST 136   // bf16 elems per A row (272B, odd multiple of 16B)
#define BST 72    // bf16 elems per B row (144B, odd multiple of 16B)
// dynamic smem layout (bytes):
//  [0,8704)       sAh (32x136 bf16)     -- reused as Ys (32x65 f32 = 8320B) after MMA
//  [8704,17408)   sAl
//  [17408,35840)  sBh (128x72 bf16)
//  [35840,54272)  sBl
//  [54272,62464)  u_s (2048 f32)
//  [62464,62720)  fst (64 f32)
#define KMAIN_SMEM 62720

__global__ void __launch_bounds__(256) k_main(const float* __restrict__ u,
                                              const float* __restrict__ Din)
{
    extern __shared__ __align__(16) unsigned char smraw[];
    __nv_bfloat16* sAh = (__nv_bfloat16*)(smraw);
    __nv_bfloat16* sAl = (__nv_bfloat16*)(smraw + 8704);
    __nv_bfloat16* sBh = (__nv_bfloat16*)(smraw + 17408);
    __nv_bfloat16* sBl = (__nv_bfloat16*)(smraw + 35840);
    float* u_s = (float*)(smraw + 54272);
    float* fst = (float*)(smraw + 62464);
    float* Ys  = (float*)(smraw);          // overlays sAh/sAl after MMA

    int row = blockIdx.x;
    int h = row & (HN-1);
    int tid = threadIdx.x;

    for (int i = tid; i < LN/4; i += 256)
        ((float4*)u_s)[i] = ((const float4*)(u + (size_t)row*LN))[i];
    if (tid < CN) fst[tid] = g_f[h*LN + tid];
    __syncthreads();

    // A = [S | U], 32 rows x 128 k, hi/lo split
    for (int i = tid; i < NC*2*D2N; i += 256) {          // S part (coalesced g_S row)
        int c = i >> 6, dd = i & 63;
        float v = g_S[(size_t)row*(NC*2*D2N) + i];
        __nv_bfloat16 hi = __float2bfloat16(v);
        sAh[c*AST + dd] = hi;
        sAl[c*AST + dd] = __float2bfloat16(v - __bfloat162float(hi));
    }
    for (int i = tid; i < LN; i += 256) {                // U part
        int c = i >> 6, m = i & 63;
        float v = u_s[i];
        __nv_bfloat16 hi = __float2bfloat16(v);
        sAh[c*AST + 64 + m] = hi;
        sAl[c*AST + 64 + m] = __float2bfloat16(v - __bfloat162float(hi));
    }
    // B = [P ; F], 128 k x 64 n, hi/lo split
    for (int i = tid; i < 4096; i += 256) {              // P part (coalesced g_P row)
        int dd = i >> 6, j = i & 63;
        float v = g_P[(size_t)h*4096 + i];
        __nv_bfloat16 hi = __float2bfloat16(v);
        sBh[dd*BST + j] = hi;
        sBl[dd*BST + j] = __float2bfloat16(v - __bfloat162float(hi));
    }
    for (int i = tid; i < 4096; i += 256) {              // F Toeplitz: F[m][j] = f[j-m]
        int m = i >> 6, j = i & 63;
        float v = (j >= m) ? fst[j - m] : 0.f;
        __nv_bfloat16 hi = __float2bfloat16(v);
        sBh[(64 + m)*BST + j] = hi;
        sBl[(64 + m)*BST + j] = __float2bfloat16(v - __bfloat162float(hi));
    }
    __syncthreads();

    // 8 warps: warp = mt*4 + np; mt in {0,1} (16 rows), np in {0..3} (16 cols = 2 n-tiles)
    int warp = tid >> 5, lane = tid & 31;
    int mt = warp >> 2;
    int np = warp & 3;
    uint32_t ah_u = (uint32_t)__cvta_generic_to_shared(sAh);
    uint32_t al_u = (uint32_t)__cvta_generic_to_shared(sAl);
    uint32_t bh_u = (uint32_t)__cvta_generic_to_shared(sBh);
    uint32_t bl_u = (uint32_t)__cvta_generic_to_shared(sBl);

    float acc[2][4];
    #pragma unroll
    for (int ni = 0; ni < 2; ni++)
        #pragma unroll
        for (int q = 0; q < 4; q++) acc[ni][q] = 0.f;

    #pragma unroll
    for (int ks = 0; ks < 8; ks++) {
        uint32_t ah[4], al[4], bh[2][2], bl[2][2];
        int arow = mt*16 + (lane & 7) + ((lane >> 3) & 1) * 8;
        int acol = ks*16 + (lane >> 4) * 8;
        ldsm_x4(ah[0], ah[1], ah[2], ah[3], ah_u + (uint32_t)((arow*AST + acol) * 2));
        ldsm_x4(al[0], al[1], al[2], al[3], al_u + (uint32_t)((arow*AST + acol) * 2));
        int brow = ks*16 + (lane & 15);
        #pragma unroll
        for (int ni = 0; ni < 2; ni++) {
            int bcol = np*16 + ni*8;
            ldsm_x2t(bh[ni][0], bh[ni][1], bh_u + (uint32_t)((brow*BST + bcol) * 2));
            ldsm_x2t(bl[ni][0], bl[ni][1], bl_u + (uint32_t)((brow*BST + bcol) * 2));
        }
        #pragma unroll
        for (int ni = 0; ni < 2; ni++) {
            mma_bf16(acc[ni], ah, bh[ni]);
            mma_bf16(acc[ni], ah, bl[ni]);
            mma_bf16(acc[ni], al, bh[ni]);
        }
    }
    __syncthreads();     // done reading sA/sB; safe to overlay Ys

    // stage Y fragments to padded smem [c][j], stride 65
    {
        int c = mt*16 + (lane >> 2);
        #pragma unroll
        for (int ni = 0; ni < 2; ni++) {
            int j = np*16 + ni*8 + (lane & 3)*2;
            Ys[c*65 + j]       = acc[ni][0];
            Ys[c*65 + j + 1]   = acc[ni][1];
            Ys[(c+8)*65 + j]   = acc[ni][2];
            Ys[(c+8)*65 + j+1] = acc[ni][3];
        }
    }
    __syncthreads();

    // epilogue: y += k0 - 0.5*u0*f + coefU*u ; GELU ; bf16 hi/lo store
    float u0f   = u_s[0];
    float coefU = Din[h] - 0.5f * fst[0];
    for (int i = tid; i < LN; i += 256) {
        int c = i >> 6, j = i & 63;
        float y = Ys[c*65 + j]
                + g_k0[h*LN + i] - 0.5f*u0f*g_f[h*LN + i]
                + coefU*u_s[i];
        float g = 0.5f * y * (1.0f + erff(y * 0.70710678118654752f));
        __nv_bfloat16 hi = __float2bfloat16(g);
        g_gh[row*LN + i] = hi;
        g_gl[row*LN + i] = __float2bfloat16(g - __bfloat162float(hi));
    }
}

// ---------------- K5: tensor-core GEMM, bf16 split, cp.async double-buffered ----------------
#define ASTR 40    // bf16 elems per A smem row (80B)
#define BSTR 136   // bf16 elems per B smem row (272B)
#define A_ST (128*ASTR)
#define B_ST (32*BSTR)

#define CP_ASYNC16(dst, src) asm volatile("cp.async.cg.shared.global [%0], [%1], 16;" :: "r"(dst), "l"(src))
#define CP_COMMIT()          asm volatile("cp.async.commit_group;" ::: "memory")
#define CP_WAIT1()           asm volatile("cp.async.wait_group 1;" ::: "memory")
#define CP_WAIT0()           asm volatile("cp.async.wait_group 0;" ::: "memory")

__device__ __forceinline__ void gemm_prefetch(int tid,
    const __nv_bfloat16* Wh_t, const __nv_bfloat16* Wl_t,
    const __nv_bfloat16* Gh_t, const __nv_bfloat16* Gl_t,
    __nv_bfloat16* ah, __nv_bfloat16* al,
    __nv_bfloat16* bh, __nv_bfloat16* bl, int k0)
{
    #pragma unroll
    for (int rpt = 0; rpt < 2; rpt++) {
        int idx = tid + rpt*256;
        int arow = idx >> 2, acol = (idx & 3) * 8;
        uint32_t da = (uint32_t)__cvta_generic_to_shared(ah + arow*ASTR + acol);
        CP_ASYNC16(da, Wh_t + (size_t)arow*HN + k0 + acol);
        da = (uint32_t)__cvta_generic_to_shared(al + arow*ASTR + acol);
        CP_ASYNC16(da, Wl_t + (size_t)arow*HN + k0 + acol);
        int brow = idx >> 4, bcol = (idx & 15) * 8;
        uint32_t db = (uint32_t)__cvta_generic_to_shared(bh + brow*BSTR + bcol);
        CP_ASYNC16(db, Gh_t + (size_t)(k0 + brow)*LN + bcol);
        db = (uint32_t)__cvta_generic_to_shared(bl + brow*BSTR + bcol);
        CP_ASYNC16(db, Gl_t + (size_t)(k0 + brow)*LN + bcol);
    }
}

__global__ void __launch_bounds__(256) k_gemm_tc(const float* __restrict__ bias,
                                                 float* __restrict__ out)
{
    extern __shared__ __align__(16) __nv_bfloat16 smp[];
    __nv_bfloat16* pAH[2] = { smp,              smp + A_ST };
    __nv_bfloat16* pAL[2] = { smp + 2*A_ST,     smp + 3*A_ST };
    __nv_bfloat16* pBH[2] = { smp + 4*A_ST,          smp + 4*A_ST + B_ST };
    __nv_bfloat16* pBL[2] = { smp + 4*A_ST + 2*B_ST, smp + 4*A_ST + 3*B_ST };

    int bz = blockIdx.z, bm = blockIdx.y, bn = blockIdx.x;
    int tid  = threadIdx.x;
    int warp = tid >> 5, lane = tid & 31;
    int wm = (warp >> 2) * 64;
    int wn = (warp & 3) * 32;

    const __nv_bfloat16* Wh_t = g_Wh + (size_t)(bm*128)*HN;
    const __nv_bfloat16* Wl_t = g_Wl + (size_t)(bm*128)*HN;
    const __nv_bfloat16* Gh_t = g_gh + (size_t)bz*HN*LN + bn*128;
    const __nv_bfloat16* Gl_t = g_gl + (size_t)bz*HN*LN + bn*128;

    float acc[4][4][4];
    #pragma unroll
    for (int i = 0; i < 4; i++)
        #pragma unroll
        for (int j = 0; j < 4; j++)
            #pragma unroll
            for (int q = 0; q < 4; q++) acc[i][j][q] = 0.f;

    gemm_prefetch(tid, Wh_t, Wl_t, Gh_t, Gl_t, pAH[0], pAL[0], pBH[0], pBL[0], 0);
    CP_COMMIT();

    for (int s = 0; s < 16; s++) {
        int cur = s & 1;
        if (s < 15) {
            gemm_prefetch(tid, Wh_t, Wl_t, Gh_t, Gl_t,
                          pAH[cur^1], pAL[cur^1], pBH[cur^1], pBL[cur^1], (s+1)*32);
            CP_COMMIT();
            CP_WAIT1();
        } else {
            CP_WAIT0();
        }
        __syncthreads();

        uint32_t ah_u = (uint32_t)__cvta_generic_to_shared(pAH[cur]);
        uint32_t al_u = (uint32_t)__cvta_generic_to_shared(pAL[cur]);
        uint32_t bh_u = (uint32_t)__cvta_generic_to_shared(pBH[cur]);
        uint32_t bl_u = (uint32_t)__cvta_generic_to_shared(pBL[cur]);

        #pragma unroll
        for (int kk = 0; kk < 32; kk += 16) {
            uint32_t ah[4][4], al[4][4], bh[4][2], bl[4][2];
            int arow = wm + (lane & 7) + ((lane >> 3) & 1) * 8;
            int acol = kk + (lane >> 4) * 8;
            #pragma unroll
            for (int mi = 0; mi < 4; mi++) {
                uint32_t ad = ah_u + (uint32_t)(((arow + mi*16)*ASTR + acol) * 2);
                ldsm_x4(ah[mi][0], ah[mi][1], ah[mi][2], ah[mi][3], ad);
                ad = al_u + (uint32_t)(((arow + mi*16)*ASTR + acol) * 2);
                ldsm_x4(al[mi][0], al[mi][1], al[mi][2], al[mi][3], ad);
            }
            int brow = kk + (lane & 15);
            #pragma unroll
            for (int ni = 0; ni < 4; ni++) {
                uint32_t bd = bh_u + (uint32_t)((brow*BSTR + wn + ni*8) * 2);
                ldsm_x2t(bh[ni][0], bh[ni][1], bd);
                bd = bl_u + (uint32_t)((brow*BSTR + wn + ni*8) * 2);
                ldsm_x2t(bl[ni][0], bl[ni][1], bd);
            }
            #pragma unroll
            for (int mi = 0; mi < 4; mi++)
                #pragma unroll
                for (int ni = 0; ni < 4; ni++) {
                    mma_bf16(acc[mi][ni], ah[mi], bh[ni]);
                    mma_bf16(acc[mi][ni], ah[mi], bl[ni]);
                    mma_bf16(acc[mi][ni], al[mi], bh[ni]);
                }
        }
        __syncthreads();
    }

    #pragma unroll
    for (int mi = 0; mi < 4; mi++) {
        int m = bm*128 + wm + mi*16 + (lane >> 2);
        float bi0 = bias[m], bi8 = bias[m + 8];
        #pragma unroll
        for (int ni = 0; ni < 4; ni++) {
            int n = bn*128 + wn + ni*8 + (lane & 3)*2;
            float2 v0 = make_float2(acc[mi][ni][0] + bi0, acc[mi][ni][1] + bi0);
            float2 v1 = make_float2(acc[mi][ni][2] + bi8, acc[mi][ni][3] + bi8);
            *(float2*)(out + (size_t)(bz*HN + m)*LN + n)     = v0;
            *(float2*)(out + (size_t)(bz*HN + m + 8)*LN + n) = v1;
        }
    }
}

// ---------------- launch ----------------
extern "C" void kernel_launch(void* const* d_in, const int* in_sizes, int n_in,
                              void* d_out, int out_size)
{
    const float* u     = (const float*)d_in[0];
    const float* a     = (const float*)d_in[1];
    const float* theta = (const float*)d_in[2];
    const float* bcoef = (const float*)d_in[3];
    const float* ccoef = (const float*)d_in[4];
    const float* x0    = (const float*)d_in[5];
    const float* Dv    = (const float*)d_in[6];
    const float* W     = (const float*)d_in[7];
    const float* bias  = (const float*)d_in[8];
    float* out = (float*)d_out;

    const int gemm_smem = (4*A_ST + 4*B_ST) * 2;   // 75776 bytes
    static int configured = 0;
    if (!configured) {
        cudaFuncSetAttribute(k_gemm_tc, cudaFuncAttributeMaxDynamicSharedMemorySize, gemm_smem);
        cudaFuncSetAttribute(k_main,    cudaFuncAttributeMaxDynamicSharedMemorySize, KMAIN_SMEM);
        configured = 1;
    }

    k_tables <<<HN, 128>>>(a, theta, bcoef, ccoef, x0);
    k_tables2<<<8192 + HN*HN/256, 256>>>(a, theta, bcoef, ccoef, W);
    k_chunkA <<<BSZ*HN, 128>>>(u);
    k_main   <<<BSZ*HN, 256, KMAIN_SMEM>>>(u, Dv);
    k_gemm_tc<<<dim3(LN/128, HN/128, BSZ), 256, gemm_smem>>>(bias, out);
}

// round 12
// speedup vs baseline: 1.1220x; 1.1220x over previous
#include <cuda_runtime.h>
#include <cuda_bf16.h>
#include <cstdint>
#include <math.h>

#define BSZ 8
#define HN  512
#define LN  2048
#define D2N 32
#define CN  64          // chunk length
#define NC  (LN/CN)     // 32 chunks

// ---------------- scratch (device globals; no allocation allowed) ----------------
__device__ __align__(16) float  g_f [HN*LN];
__device__ __align__(16) float  g_k0[HN*LN];
__device__ float2               g_V [HN*CN*D2N];      // [h][m][d] = w^{C-1-m}
__device__ __align__(16) float  g_P [HN*2*D2N*CN];    // [h][dd][j]
__device__ float2               g_WC[HN*D2N];         // w^C
__device__ __align__(16) float  g_S [BSZ*HN*NC*2*D2N];
__device__ __align__(16) __nv_bfloat16 g_Wh[HN*HN], g_Wl[HN*HN];
__device__ __align__(16) __nv_bfloat16 g_gh[BSZ*HN*LN], g_gl[BSZ*HN*LN];
__device__ __align__(16) __nv_bfloat16 g_Bh[HN*128*64], g_Bl[HN*128*64];  // [h][k][j] = [P;F] split

// ---------------- shared mma/ldsm helpers ----------------
__device__ __forceinline__ void ldsm_x4(uint32_t &r0, uint32_t &r1, uint32_t &r2, uint32_t &r3,
                                        uint32_t addr) {
    asm volatile("ldmatrix.sync.aligned.m8n8.x4.shared.b16 {%0,%1,%2,%3}, [%4];"
                 : "=r"(r0), "=r"(r1), "=r"(r2), "=r"(r3) : "r"(addr));
}
__device__ __forceinline__ void ldsm_x2t(uint32_t &r0, uint32_t &r1, uint32_t addr) {
    asm volatile("ldmatrix.sync.aligned.m8n8.x2.trans.shared.b16 {%0,%1}, [%2];"
                 : "=r"(r0), "=r"(r1) : "r"(addr));
}
__device__ __forceinline__ void mma_bf16(float* c, const uint32_t* a, const uint32_t* b) {
    asm volatile("mma.sync.aligned.m16n8k16.row.col.f32.bf16.bf16.f32 "
                 "{%0,%1,%2,%3},{%4,%5,%6,%7},{%8,%9},{%0,%1,%2,%3};"
                 : "+f"(c[0]), "+f"(c[1]), "+f"(c[2]), "+f"(c[3])
                 : "r"(a[0]), "r"(a[1]), "r"(a[2]), "r"(a[3]), "r"(b[0]), "r"(b[1]));
}

#define CP_ASYNC16(dst, src) asm volatile("cp.async.cg.shared.global [%0], [%1], 16;" :: "r"(dst), "l"(src))
#define CP_COMMIT()          asm volatile("cp.async.commit_group;" ::: "memory")
#define CP_WAIT1()           asm volatile("cp.async.wait_group 1;" ::: "memory")
#define CP_WAIT0()           asm volatile("cp.async.wait_group 0;" ::: "memory")

// ---------------- K1: f/k0 grid via phasor rotation ----------------
__global__ void __launch_bounds__(128) k_tables(const float* __restrict__ a,
                                                const float* __restrict__ th,
                                                const float* __restrict__ bb,
                                                const float* __restrict__ cc,
                                                const float* __restrict__ x0)
{
    int h = blockIdx.x;
    __shared__ float4 tab[D2N];
    __shared__ float s_aa[D2N], s_th[D2N];
    int tid = threadIdx.x;
    const float T = 1.0f / (float)(LN - 1);
    if (tid < D2N) {
        float aa = -fabsf(a[h*D2N + tid]);
        float t0 = th[h*D2N + tid];
        float q  = bb[h*D2N + tid] * cc[h*D2N + tid];
        float cx = cc[h*D2N + tid] * x0[h*D2N + tid];
        s_aa[tid] = aa; s_th[tid] = t0;
        float zs = 128.0f * T;
        float e = __expf(aa*zs);
        float si, co; __sincosf(t0*zs, &si, &co);
        tab[tid] = make_float4(e*co, e*si, q, cx);
    }
    __syncthreads();

    float z = T * (float)tid;
    float vr[D2N], vi[D2N];
    #pragma unroll
    for (int d = 0; d < D2N; d++) {
        float e = __expf(s_aa[d]*z);
        float si, co; __sincosf(s_th[d]*z, &si, &co);
        vr[d] = e*co; vi[d] = e*si;
    }
    for (int s = 0; s < 16; s++) {
        float fa = 0.f, ka = 0.f;
        #pragma unroll
        for (int d = 0; d < D2N; d++) {
            float4 t = tab[d];
            fa += t.z * vr[d];
            ka += t.w * vr[d];
            float nr = vr[d]*t.x - vi[d]*t.y;
            vi[d]    = vr[d]*t.y + vi[d]*t.x;
            vr[d] = nr;
        }
        g_f [h*LN + tid + 128*s] = 2.0f*T*fa;
        g_k0[h*LN + tid + 128*s] = 2.0f*ka;
    }
}

// ---------------- K1b: V/P/WC tables + W bf16 split, merged ----------------
__global__ void k_tables2(const float* __restrict__ a, const float* __restrict__ th,
                          const float* __restrict__ bb, const float* __restrict__ cc,
                          const float* __restrict__ W)
{
    int bid = blockIdx.x;
    if (bid >= 8192) {
        int i = (bid - 8192)*256 + threadIdx.x;
        float w = W[i];
        __nv_bfloat16 hi = __float2bfloat16(w);
        g_Wh[i] = hi;
        g_Wl[i] = __float2bfloat16(w - __bfloat162float(hi));
        return;
    }
    int t = bid*256 + threadIdx.x;
    int which = t >> 20;
    int r = t & 0xFFFFF;
    const float T = 1.0f / (float)(LN - 1);
    if (which == 0) {
        int d = r & 31, m = (r >> 5) & 63, h = r >> 11;
        float aa = -fabsf(a[h*D2N + d]);
        float t0 = th[h*D2N + d];
        float k = (float)(CN - 1 - m);
        float e = __expf(aa*T*k);
        float si, co; __sincosf(t0*T*k, &si, &co);
        g_V[(h*CN + m)*D2N + d] = make_float2(e*co, e*si);
        if (m == 0) {
            float kc = (float)CN;
            float ec = __expf(aa*T*kc);
            float s2, c2; __sincosf(t0*T*kc, &s2, &c2);
            g_WC[h*D2N + d] = make_float2(ec*c2, ec*s2);
        }
    } else {
        int j = r & 63, d = (r >> 6) & 31, h = r >> 11;
        float aa = -fabsf(a[h*D2N + d]);
        float t0 = th[h*D2N + d];
        float q  = bb[h*D2N + d] * cc[h*D2N + d];
        float k = (float)(j + 1);
        float e = __expf(aa*T*k);
        float si, co; __sincosf(t0*T*k, &si, &co);
        g_P[(h*2*D2N + d      )*CN + j] =  2.0f*T*q*e*co;
        g_P[(h*2*D2N + D2N + d)*CN + j] = -2.0f*T*q*e*si;
    }
}

// ---------------- K1c: per-h B operand [P;F] bf16 hi/lo split ----------------
__global__ void __launch_bounds__(256) k_prepB()
{
    int h = blockIdx.x;
    __shared__ float fsh[CN];
    int tid = threadIdx.x;
    if (tid < CN) fsh[tid] = g_f[h*LN + tid];
    __syncthreads();
    // P part: rows k=0..63 (dd), j=0..63
    for (int i = tid; i < 4096; i += 256) {
        float v = g_P[(size_t)h*4096 + i];
        __nv_bfloat16 hi = __float2bfloat16(v);
        g_Bh[(size_t)h*8192 + i] = hi;
        g_Bl[(size_t)h*8192 + i] = __float2bfloat16(v - __bfloat162float(hi));
    }
    // F Toeplitz part: rows k=64+m, F[m][j] = f[j-m] (j>=m)
    for (int i = tid; i < 4096; i += 256) {
        int m = i >> 6, j = i & 63;
        float v = (j >= m) ? fsh[j - m] : 0.f;
        __nv_bfloat16 hi = __float2bfloat16(v);
        g_Bh[(size_t)h*8192 + 4096 + i] = hi;
        g_Bl[(size_t)h*8192 + 4096 + i] = __float2bfloat16(v - __bfloat162float(hi));
    }
}

// ---------------- K2: chunk states, register-resident A + 2-level scan ----------------
__global__ void __launch_bounds__(128) k_chunkA(const float* __restrict__ u)
{
    int row = blockIdx.x;
    int h = row & (HN-1);
    __shared__ float  u_s[LN];
    __shared__ float2 V_s[CN*D2N];
    __shared__ float2 Tex[4][D2N];
    __shared__ float2 Off[4][D2N];
    int tid = threadIdx.x;
    for (int i = tid; i < LN/4; i += 128)
        ((float4*)u_s)[i] = ((const float4*)(u + row*LN))[i];
    const float4* Vg4 = (const float4*)(g_V + h*CN*D2N);
    for (int i = tid; i < CN*D2N/2; i += 128)
        ((float4*)V_s)[i] = Vg4[i];
    __syncthreads();

    int d = tid & 31;
    int w = tid >> 5;
    float ar[8] = {}, ai[8] = {};
    #pragma unroll 2
    for (int m4 = 0; m4 < CN; m4 += 4) {
        float4 uv[8];
        #pragma unroll
        for (int c = 0; c < 8; c++)
            uv[c] = *(const float4*)&u_s[(8*w + c)*CN + m4];
        #pragma unroll
        for (int mm = 0; mm < 4; mm++) {
            float2 v = V_s[(m4+mm)*D2N + d];
            #pragma unroll
            for (int c = 0; c < 8; c++) {
                float um = ((const float*)&uv[c])[mm];
                ar[c] += v.x * um;
                ai[c] += v.y * um;
            }
        }
    }

    float2 wc = g_WC[h*D2N + d];
    float Sr[8], Si[8];
    {
        float sr = 0.f, si = 0.f;
        #pragma unroll
        for (int c = 0; c < 8; c++) {
            Sr[c] = sr; Si[c] = si;
            float nsr = wc.x*sr - wc.y*si + ar[c];
            si        = wc.x*si + wc.y*sr + ai[c];
            sr = nsr;
        }
        Tex[w][d] = make_float2(sr, si);
    }
    __syncthreads();

    if (w == 0) {
        float2 w2 = make_float2(wc.x*wc.x - wc.y*wc.y, 2.f*wc.x*wc.y);
        float2 w4 = make_float2(w2.x*w2.x - w2.y*w2.y, 2.f*w2.x*w2.y);
        float2 w8 = make_float2(w4.x*w4.x - w4.y*w4.y, 2.f*w4.x*w4.y);
        float orr = 0.f, oi = 0.f;
        #pragma unroll
        for (int ww = 0; ww < 4; ww++) {
            Off[ww][d] = make_float2(orr, oi);
            float2 t = Tex[ww][d];
            float no = w8.x*orr - w8.y*oi + t.x;
            oi       = w8.x*oi + w8.y*orr + t.y;
            orr = no;
        }
    }
    __syncthreads();

    float2 off = Off[w][d];
    float cr = off.x, ci = off.y;
    #pragma unroll
    for (int c = 0; c < 8; c++) {
        int idx = (row*NC + 8*w + c)*2*D2N;
        g_S[idx + d]       = cr + Sr[c];
        g_S[idx + D2N + d] = ci + Si[c];
        float ncr = wc.x*cr - wc.y*ci;
        ci        = wc.x*ci + wc.y*cr;
        cr = ncr;
    }
}

// ---------------- K4: tensor-core row GEMM  Y = [S|U](32x128) @ [P;F](128x64) ----------------
#define AST 136   // bf16 elems per A row (272B)
#define BST 72    // bf16 elems per B row (144B)
// smem: sAh [0,8704) | sAl [8704,17408) | sBh [17408,35840) | sBl [35840,54272)
// Ys (32x65 f32 = 8320B) overlays sAh after MMA.
#define KMAIN_SMEM 54272

__global__ void __launch_bounds__(256) k_main(const float* __restrict__ u,
                                              const float* __restrict__ Din)
{
    extern __shared__ __align__(16) unsigned char smraw[];
    __nv_bfloat16* sAh = (__nv_bfloat16*)(smraw);
    __nv_bfloat16* sAl = (__nv_bfloat16*)(smraw + 8704);
    __nv_bfloat16* sBh = (__nv_bfloat16*)(smraw + 17408);
    __nv_bfloat16* sBl = (__nv_bfloat16*)(smraw + 35840);
    float* Ys  = (float*)(smraw);

    int row = blockIdx.x;
    int h = row & (HN-1);
    int tid = threadIdx.x;

    // 1) async B load: 128 rows x 64 elems, row k -> smem stride BST
    {
        const __nv_bfloat16* Bh = g_Bh + (size_t)h*8192;
        const __nv_bfloat16* Bl = g_Bl + (size_t)h*8192;
        #pragma unroll
        for (int r = 0; r < 4; r++) {
            int idx = tid + r*256;            // 1024 chunks of 8 bf16
            int k = idx >> 3, j8 = (idx & 7) * 8;
            uint32_t dst = (uint32_t)__cvta_generic_to_shared(sBh + k*BST + j8);
            CP_ASYNC16(dst, Bh + idx*8);
            dst = (uint32_t)__cvta_generic_to_shared(sBl + k*BST + j8);
            CP_ASYNC16(dst, Bl + idx*8);
        }
        CP_COMMIT();
    }

    // 2) A prep: A = [S | U], 32 rows x 128 k, hi/lo split (coalesced global reads)
    const float* Srow = g_S + (size_t)row*(NC*2*D2N);
    const float* urow = u + (size_t)row*LN;
    for (int i = tid; i < NC*2*D2N; i += 256) {
        int c = i >> 6, dd = i & 63;
        float v = Srow[i];
        __nv_bfloat16 hi = __float2bfloat16(v);
        sAh[c*AST + dd] = hi;
        sAl[c*AST + dd] = __float2bfloat16(v - __bfloat162float(hi));
    }
    for (int i = tid; i < LN; i += 256) {
        int c = i >> 6, m = i & 63;
        float v = urow[i];
        __nv_bfloat16 hi = __float2bfloat16(v);
        sAh[c*AST + 64 + m] = hi;
        sAl[c*AST + 64 + m] = __float2bfloat16(v - __bfloat162float(hi));
    }
    CP_WAIT0();
    __syncthreads();

    // 3) MMA: 8 warps, warp = mt*4+np
    int warp = tid >> 5, lane = tid & 31;
    int mt = warp >> 2;
    int np = warp & 3;
    uint32_t ah_u = (uint32_t)__cvta_generic_to_shared(sAh);
    uint32_t al_u = (uint32_t)__cvta_generic_to_shared(sAl);
    uint32_t bh_u = (uint32_t)__cvta_generic_to_shared(sBh);
    uint32_t bl_u = (uint32_t)__cvta_generic_to_shared(sBl);

    float acc[2][4];
    #pragma unroll
    for (int ni = 0; ni < 2; ni++)
        #pragma unroll
        for (int q = 0; q < 4; q++) acc[ni][q] = 0.f;

    #pragma unroll
    for (int ks = 0; ks < 8; ks++) {
        uint32_t ah[4], al[4], bh[2][2], bl[2][2];
        int arow = mt*16 + (lane & 7) + ((lane >> 3) & 1) * 8;
        int acol = ks*16 + (lane >> 4) * 8;
        ldsm_x4(ah[0], ah[1], ah[2], ah[3], ah_u + (uint32_t)((arow*AST + acol) * 2));
        ldsm_x4(al[0], al[1], al[2], al[3], al_u + (uint32_t)((arow*AST + acol) * 2));
        int brow = ks*16 + (lane & 15);
        #pragma unroll
        for (int ni = 0; ni < 2; ni++) {
            int bcol = np*16 + ni*8;
            ldsm_x2t(bh[ni][0], bh[ni][1], bh_u + (uint32_t)((brow*BST + bcol) * 2));
            ldsm_x2t(bl[ni][0], bl[ni][1], bl_u + (uint32_t)((brow*BST + bcol) * 2));
        }
        #pragma unroll
        for (int ni = 0; ni < 2; ni++) {
            mma_bf16(acc[ni], ah, bh[ni]);
            mma_bf16(acc[ni], ah, bl[ni]);
            mma_bf16(acc[ni], al, bh[ni]);
        }
    }
    __syncthreads();     // done reading sA; overlay Ys

    {
        int c = mt*16 + (lane >> 2);
        #pragma unroll
        for (int ni = 0; ni < 2; ni++) {
            int j = np*16 + ni*8 + (lane & 3)*2;
            Ys[c*65 + j]       = acc[ni][0];
            Ys[c*65 + j + 1]   = acc[ni][1];
            Ys[(c+8)*65 + j]   = acc[ni][2];
            Ys[(c+8)*65 + j+1] = acc[ni][3];
        }
    }
    __syncthreads();

    // 4) epilogue: y += k0 - 0.5*u0*f + coefU*u ; GELU ; bf16 hi/lo store
    float u0f   = urow[0];
    float coefU = Din[h] - 0.5f * g_f[h*LN];
    for (int i = tid; i < LN; i += 256) {
        int c = i >> 6, j = i & 63;
        float y = Ys[c*65 + j]
                + g_k0[h*LN + i] - 0.5f*u0f*g_f[h*LN + i]
                + coefU*urow[i];
        float g = 0.5f * y * (1.0f + erff(y * 0.70710678118654752f));
        __nv_bfloat16 hi = __float2bfloat16(g);
        g_gh[row*LN + i] = hi;
        g_gl[row*LN + i] = __float2bfloat16(g - __bfloat162float(hi));
    }
}

// ---------------- K5: tensor-core GEMM, bf16 split, cp.async double-buffered ----------------
#define ASTR 40    // bf16 elems per A smem row (80B)
#define BSTR 136   // bf16 elems per B smem row (272B)
#define A_ST (128*ASTR)
#define B_ST (32*BSTR)

__device__ __forceinline__ void gemm_prefetch(int tid,
    const __nv_bfloat16* Wh_t, const __nv_bfloat16* Wl_t,
    const __nv_bfloat16* Gh_t, const __nv_bfloat16* Gl_t,
    __nv_bfloat16* ah, __nv_bfloat16* al,
    __nv_bfloat16* bh, __nv_bfloat16* bl, int k0)
{
    #pragma unroll
    for (int rpt = 0; rpt < 2; rpt++) {
        int idx = tid + rpt*256;
        int arow = idx >> 2, acol = (idx & 3) * 8;
        uint32_t da = (uint32_t)__cvta_generic_to_shared(ah + arow*ASTR + acol);
        CP_ASYNC16(da, Wh_t + (size_t)arow*HN + k0 + acol);
        da = (uint32_t)__cvta_generic_to_shared(al + arow*ASTR + acol);
        CP_ASYNC16(da, Wl_t + (size_t)arow*HN + k0 + acol);
        int brow = idx >> 4, bcol = (idx & 15) * 8;
        uint32_t db = (uint32_t)__cvta_generic_to_shared(bh + brow*BSTR + bcol);
        CP_ASYNC16(db, Gh_t + (size_t)(k0 + brow)*LN + bcol);
        db = (uint32_t)__cvta_generic_to_shared(bl + brow*BSTR + bcol);
        CP_ASYNC16(db, Gl_t + (size_t)(k0 + brow)*LN + bcol);
    }
}

__global__ void __launch_bounds__(256) k_gemm_tc(const float* __restrict__ bias,
                                                 float* __restrict__ out)
{
    extern __shared__ __align__(16) __nv_bfloat16 smp[];
    __nv_bfloat16* pAH[2] = { smp,              smp + A_ST };
    __nv_bfloat16* pAL[2] = { smp + 2*A_ST,     smp + 3*A_ST };
    __nv_bfloat16* pBH[2] = { smp + 4*A_ST,          smp + 4*A_ST + B_ST };
    __nv_bfloat16* pBL[2] = { smp + 4*A_ST + 2*B_ST, smp + 4*A_ST + 3*B_ST };

    int bz = blockIdx.z, bm = blockIdx.y, bn = blockIdx.x;
    int tid  = threadIdx.x;
    int warp = tid >> 5, lane = tid & 31;
    int wm = (warp >> 2) * 64;
    int wn = (warp & 3) * 32;

    const __nv_bfloat16* Wh_t = g_Wh + (size_t)(bm*128)*HN;
    const __nv_bfloat16* Wl_t = g_Wl + (size_t)(bm*128)*HN;
    const __nv_bfloat16* Gh_t = g_gh + (size_t)bz*HN*LN + bn*128;
    const __nv_bfloat16* Gl_t = g_gl + (size_t)bz*HN*LN + bn*128;

    float acc[4][4][4];
    #pragma unroll
    for (int i = 0; i < 4; i++)
        #pragma unroll
        for (int j = 0; j < 4; j++)
            #pragma unroll
            for (int q = 0; q < 4; q++) acc[i][j][q] = 0.f;

    gemm_prefetch(tid, Wh_t, Wl_t, Gh_t, Gl_t, pAH[0], pAL[0], pBH[0], pBL[0], 0);
    CP_COMMIT();

    for (int s = 0; s < 16; s++) {
        int cur = s & 1;
        if (s < 15) {
            gemm_prefetch(tid, Wh_t, Wl_t, Gh_t, Gl_t,
                          pAH[cur^1], pAL[cur^1], pBH[cur^1], pBL[cur^1], (s+1)*32);
            CP_COMMIT();
            CP_WAIT1();
        } else {
            CP_WAIT0();
        }
        __syncthreads();

        uint32_t ah_u = (uint32_t)__cvta_generic_to_shared(pAH[cur]);
        uint32_t al_u = (uint32_t)__cvta_generic_to_shared(pAL[cur]);
        uint32_t bh_u = (uint32_t)__cvta_generic_to_shared(pBH[cur]);
        uint32_t bl_u = (uint32_t)__cvta_generic_to_shared(pBL[cur]);

        #pragma unroll
        for (int kk = 0; kk < 32; kk += 16) {
            uint32_t ah[4][4], al[4][4], bh[4][2], bl[4][2];
            int arow = wm + (lane & 7) + ((lane >> 3) & 1) * 8;
            int acol = kk + (lane >> 4) * 8;
            #pragma unroll
            for (int mi = 0; mi < 4; mi++) {
                uint32_t ad = ah_u + (uint32_t)(((arow + mi*16)*ASTR + acol) * 2);
                ldsm_x4(ah[mi][0], ah[mi][1], ah[mi][2], ah[mi][3], ad);
                ad = al_u + (uint32_t)(((arow + mi*16)*ASTR + acol) * 2);
                ldsm_x4(al[mi][0], al[mi][1], al[mi][2], al[mi][3], ad);
            }
            int brow = kk + (lane & 15);
            #pragma unroll
            for (int ni = 0; ni < 4; ni++) {
                uint32_t bd = bh_u + (uint32_t)((brow*BSTR + wn + ni*8) * 2);
                ldsm_x2t(bh[ni][0], bh[ni][1], bd);
                bd = bl_u + (uint32_t)((brow*BSTR + wn + ni*8) * 2);
                ldsm_x2t(bl[ni][0], bl[ni][1], bd);
            }
            #pragma unroll
            for (int mi = 0; mi < 4; mi++)
                #pragma unroll
                for (int ni = 0; ni < 4; ni++) {
                    mma_bf16(acc[mi][ni], ah[mi], bh[ni]);
                    mma_bf16(acc[mi][ni], ah[mi], bl[ni]);
                    mma_bf16(acc[mi][ni], al[mi], bh[ni]);
                }
        }
        __syncthreads();
    }

    #pragma unroll
    for (int mi = 0; mi < 4; mi++) {
        int m = bm*128 + wm + mi*16 + (lane >> 2);
        float bi0 = bias[m], bi8 = bias[m + 8];
        #pragma unroll
        for (int ni = 0; ni < 4; ni++) {
            int n = bn*128 + wn + ni*8 + (lane & 3)*2;
            float2 v0 = make_float2(acc[mi][ni][0] + bi0, acc[mi][ni][1] + bi0);
            float2 v1 = make_float2(acc[mi][ni][2] + bi8, acc[mi][ni][3] + bi8);
            *(float2*)(out + (size_t)(bz*HN + m)*LN + n)     = v0;
            *(float2*)(out + (size_t)(bz*HN + m + 8)*LN + n) = v1;
        }
    }
}

// ---------------- launch ----------------
extern "C" void kernel_launch(void* const* d_in, const int* in_sizes, int n_in,
                              void* d_out, int out_size)
{
    const float* u     = (const float*)d_in[0];
    const float* a     = (const float*)d_in[1];
    const float* theta = (const float*)d_in[2];
    const float* bcoef = (const float*)d_in[3];
    const float* ccoef = (const float*)d_in[4];
    const float* x0    = (const float*)d_in[5];
    const float* Dv    = (const float*)d_in[6];
    const float* W     = (const float*)d_in[7];
    const float* bias  = (const float*)d_in[8];
    float* out = (float*)d_out;

    const int gemm_smem = (4*A_ST + 4*B_ST) * 2;   // 75776 bytes
    static int configured = 0;
    if (!configured) {
        cudaFuncSetAttribute(k_gemm_tc, cudaFuncAttributeMaxDynamicSharedMemorySize, gemm_smem);
        cudaFuncSetAttribute(k_main,    cudaFuncAttributeMaxDynamicSharedMemorySize, KMAIN_SMEM);
        configured = 1;
    }

    k_tables <<<HN, 128>>>(a, theta, bcoef, ccoef, x0);
    k_tables2<<<8192 + HN*HN/256, 256>>>(a, theta, bcoef, ccoef, W);
    k_prepB  <<<HN, 256>>>();
    k_chunkA <<<BSZ*HN, 128>>>(u);
    k_main   <<<BSZ*HN, 256, KMAIN_SMEM>>>(u, Dv);
    k_gemm_tc<<<dim3(LN/128, HN/128, BSZ), 256, gemm_smem>>>(bias, out);
}